// round 6
// baseline (speedup 1.0000x reference)
#include <cuda_runtime.h>
#include <cstdint>

typedef unsigned long long ull;

#define NB      1024
#define N1      64
#define N2      128
#define DD      256
#define LN_EPS  1e-5f
#define ISCALE  0.0625f     // D^-0.5 = 1/16
#define NT      512

// SMEM strides (in floats). 258 => consecutive rows shift banks by 2 (conflict-free
// column access, 8-byte aligned for float2). 132 => conflict-free-ish I access.
#define S_H 258
#define S_I 132

static constexpr int SH2_OFF     = N1 * S_H;              // 16512 floats
static constexpr int SI_OFF      = SH2_OFF + N2 * S_H;    // 49536 floats
static constexpr int SMEM_FLOATS = SI_OFF + N1 * S_I;     // 57984 floats
static constexpr int SMEM_BYTES  = SMEM_FLOATS * 4;       // 231936 B

// ---- packed fp32x2 helpers (Blackwell FFMA2 path) ----
__device__ __forceinline__ ull fma2(ull a, ull b, ull c) {
    ull d;
    asm("fma.rn.f32x2 %0, %1, %2, %3;" : "=l"(d) : "l"(a), "l"(b), "l"(c));
    return d;
}
__device__ __forceinline__ ull dup2(float x) {
    unsigned xu = __float_as_uint(x);
    ull r;
    asm("mov.b64 %0, {%1, %1};" : "=l"(r) : "r"(xu));
    return r;
}
__device__ __forceinline__ void unpack2(ull v, float& lo, float& hi) {
    unsigned a, b;
    asm("mov.b64 {%0, %1}, %2;" : "=r"(a), "=r"(b) : "l"(v));
    lo = __uint_as_float(a);
    hi = __uint_as_float(b);
}
__device__ __forceinline__ ull lds64(const float* p) {
    return *reinterpret_cast<const ull*>(p);
}

// LayerNorm over a warp-distributed row (8 values/thread, cols c = 2*lane+64*j+{0,1})
__device__ __forceinline__ void ln_store(const ull acc[4], const float gx[8],
                                         const float bx[8], float2* orow, int lane)
{
    float x[8];
    #pragma unroll
    for (int j = 0; j < 4; ++j) unpack2(acc[j], x[2 * j], x[2 * j + 1]);
    float s = 0.f, ss = 0.f;
    #pragma unroll
    for (int i = 0; i < 8; ++i) { s += x[i]; ss += x[i] * x[i]; }
    #pragma unroll
    for (int o = 16; o; o >>= 1) {
        s  += __shfl_xor_sync(0xffffffffu, s,  o);
        ss += __shfl_xor_sync(0xffffffffu, ss, o);
    }
    float mu  = s * (1.0f / 256.0f);
    float var = ss * (1.0f / 256.0f) - mu * mu;
    float inv = rsqrtf(var + LN_EPS);
    #pragma unroll
    for (int j = 0; j < 4; ++j) {
        float2 o;
        o.x = (x[2 * j]     - mu) * inv * gx[2 * j]     + bx[2 * j];
        o.y = (x[2 * j + 1] - mu) * inv * gx[2 * j + 1] + bx[2 * j + 1];
        orow[128 + lane + 32 * j] = o;
    }
}

__global__ void __launch_bounds__(NT, 1)
interaction_kernel(const float* __restrict__ h1g, const float* __restrict__ h2g,
                   const float* __restrict__ gam, const float* __restrict__ bet,
                   float* __restrict__ out)
{
    extern __shared__ float sm[];
    float* sh1 = sm;              // [64][S_H]
    float* sh2 = sm + SH2_OFF;    // [128][S_H]
    float* sI  = sm + SI_OFF;     // [64][S_I]

    const int tid  = threadIdx.x;
    const int lane = tid & 31;
    const int warp = tid >> 5;    // 0..15
    const int g    = blockIdx.x;

    const float4* h1v = reinterpret_cast<const float4*>(h1g) + (size_t)g * (N1 * DD / 4);
    const float4* h2v = reinterpret_cast<const float4*>(h2g) + (size_t)g * (N2 * DD / 4);
    float4* o1x = reinterpret_cast<float4*>(out) + (size_t)g * (N1 * DD / 2);   // rows of 128 float4
    float4* o2x = reinterpret_cast<float4*>(out) + (size_t)NB * (N1 * DD / 2)
                                                 + (size_t)g * (N2 * DD / 2);
    float2* o1 = reinterpret_cast<float2*>(out) + (size_t)g * (N1 * DD);
    float2* o2 = reinterpret_cast<float2*>(out) + (size_t)NB * N1 * DD
                                               + (size_t)g * (N2 * DD);

    // ---------------- Phase 1: global -> SMEM (LDG.128), fused concat-copy ----------------
    #pragma unroll 4
    for (int it = 0; it < (N1 * DD / 4) / NT; ++it) {    // 8 iters
        int idx = it * NT + tid;
        int row = idx >> 6, c4 = idx & 63;
        float4 v = h1v[idx];
        float* d = &sh1[row * S_H + 4 * c4];
        *reinterpret_cast<float2*>(d)     = make_float2(v.x, v.y);
        *reinterpret_cast<float2*>(d + 2) = make_float2(v.z, v.w);
        o1x[(size_t)row * 128 + c4] = v;                 // h1_enh[:, 0:256] = h1
    }
    #pragma unroll 4
    for (int it = 0; it < (N2 * DD / 4) / NT; ++it) {    // 16 iters
        int idx = it * NT + tid;
        int row = idx >> 6, c4 = idx & 63;
        float4 v = h2v[idx];
        float* d = &sh2[row * S_H + 4 * c4];
        *reinterpret_cast<float2*>(d)     = make_float2(v.x, v.y);
        *reinterpret_cast<float2*>(d + 2) = make_float2(v.z, v.w);
        o2x[(size_t)row * 128 + c4] = v;                 // h2_enh[:, 0:256] = h2
    }
    __syncthreads();

    // ---------------- Phase 2: GEMM1  I[64,128] = clip(h1 @ h2^T * scale) -----------------
    // K-split across two 256-thread groups; each thread: 4 rows x 8 cols, K packed f32x2.
    {
        const int grp = tid >> 8;        // 0 or 1: K half
        const int t   = tid & 255;
        const int tr  = t >> 4;          // 0..15 -> rows tr*4 .. tr*4+3
        const int tc  = t & 15;          // cols tc + 16*j
        const int kb  = grp * (DD / 2);

        ull acc[4][8];
        #pragma unroll
        for (int i = 0; i < 4; ++i)
            #pragma unroll
            for (int j = 0; j < 8; ++j) acc[i][j] = 0ull;

        const float* a_base = sh1 + (tr * 4) * S_H + kb;
        const float* b_base = sh2 + tc * S_H + kb;

        #pragma unroll 1
        for (int d = 0; d < DD / 2; d += 2) {
            ull a2[4], b2[8];
            #pragma unroll
            for (int i = 0; i < 4; ++i) a2[i] = lds64(a_base + i * S_H + d);
            #pragma unroll
            for (int j = 0; j < 8; ++j) b2[j] = lds64(b_base + j * 16 * S_H + d);
            #pragma unroll
            for (int i = 0; i < 4; ++i)
                #pragma unroll
                for (int j = 0; j < 8; ++j)
                    acc[i][j] = fma2(a2[i], b2[j], acc[i][j]);
        }

        if (grp == 1) {     // store raw partials
            #pragma unroll
            for (int i = 0; i < 4; ++i)
                #pragma unroll
                for (int j = 0; j < 8; ++j) {
                    float lo, hi; unpack2(acc[i][j], lo, hi);
                    sI[(tr * 4 + i) * S_I + tc + 16 * j] = lo + hi;
                }
        }
        __syncthreads();
        if (grp == 0) {     // combine + scale + clip
            #pragma unroll
            for (int i = 0; i < 4; ++i)
                #pragma unroll
                for (int j = 0; j < 8; ++j) {
                    float lo, hi; unpack2(acc[i][j], lo, hi);
                    float v = (lo + hi + sI[(tr * 4 + i) * S_I + tc + 16 * j]) * ISCALE;
                    v = fminf(fmaxf(v, -10.0f), 10.0f);
                    sI[(tr * 4 + i) * S_I + tc + 16 * j] = v;
                }
        }
        __syncthreads();
    }

    // gamma/beta for this lane's 8 columns: c = 2*lane + 64*j + {0,1}
    float gx[8], bx[8];
    {
        const float2* gv = reinterpret_cast<const float2*>(gam);
        const float2* bv = reinterpret_cast<const float2*>(bet);
        #pragma unroll
        for (int j = 0; j < 4; ++j) {
            float2 gj = gv[lane + 32 * j]; gx[2 * j] = gj.x; gx[2 * j + 1] = gj.y;
            float2 bj = bv[lane + 32 * j]; bx[2 * j] = bj.x; bx[2 * j + 1] = bj.y;
        }
    }

    // ---------------- Phase 3: GEMM2  h1_int = LN(I @ h2)  (4 rows / warp) ----------------
    {
        const int n0 = warp * 4;
        ull acc[4][4];
        #pragma unroll
        for (int r = 0; r < 4; ++r)
            #pragma unroll
            for (int j = 0; j < 4; ++j) acc[r][j] = 0ull;

        #pragma unroll 1
        for (int k = 0; k < N2; k += 2) {
            ull bb0[4], bb1[4];
            #pragma unroll
            for (int j = 0; j < 4; ++j) {
                bb0[j] = lds64(sh2 + k * S_H + 2 * lane + 64 * j);
                bb1[j] = lds64(sh2 + (k + 1) * S_H + 2 * lane + 64 * j);
            }
            #pragma unroll
            for (int r = 0; r < 4; ++r) {
                float2 iv = *reinterpret_cast<const float2*>(sI + (n0 + r) * S_I + k);
                ull i0 = dup2(iv.x), i1 = dup2(iv.y);
                #pragma unroll
                for (int j = 0; j < 4; ++j) {
                    acc[r][j] = fma2(i0, bb0[j], acc[r][j]);
                    acc[r][j] = fma2(i1, bb1[j], acc[r][j]);
                }
            }
        }
        #pragma unroll
        for (int r = 0; r < 4; ++r)
            ln_store(acc[r], gx, bx, o1 + (size_t)(n0 + r) * 256, lane);
    }

    // ---------------- Phase 4: GEMM3  h2_int = LN(I^T @ h1)  (8 rows / warp) --------------
    {
        const int m0 = warp * 8;
        ull acc[8][4];
        #pragma unroll
        for (int r = 0; r < 8; ++r)
            #pragma unroll
            for (int j = 0; j < 4; ++j) acc[r][j] = 0ull;

        #pragma unroll 1
        for (int k = 0; k < N1; k += 2) {
            ull bb0[4], bb1[4];
            #pragma unroll
            for (int j = 0; j < 4; ++j) {
                bb0[j] = lds64(sh1 + k * S_H + 2 * lane + 64 * j);
                bb1[j] = lds64(sh1 + (k + 1) * S_H + 2 * lane + 64 * j);
            }
            // I[k, m0..m0+7] and I[k+1, m0..m0+7]: contiguous -> float4 broadcast loads
            float4 iA0 = *reinterpret_cast<const float4*>(sI + k * S_I + m0);
            float4 iA1 = *reinterpret_cast<const float4*>(sI + k * S_I + m0 + 4);
            float4 iB0 = *reinterpret_cast<const float4*>(sI + (k + 1) * S_I + m0);
            float4 iB1 = *reinterpret_cast<const float4*>(sI + (k + 1) * S_I + m0 + 4);
            float ia[8] = {iA0.x, iA0.y, iA0.z, iA0.w, iA1.x, iA1.y, iA1.z, iA1.w};
            float ib[8] = {iB0.x, iB0.y, iB0.z, iB0.w, iB1.x, iB1.y, iB1.z, iB1.w};
            #pragma unroll
            for (int r = 0; r < 8; ++r) {
                ull i0 = dup2(ia[r]), i1 = dup2(ib[r]);
                #pragma unroll
                for (int j = 0; j < 4; ++j) {
                    acc[r][j] = fma2(i0, bb0[j], acc[r][j]);
                    acc[r][j] = fma2(i1, bb1[j], acc[r][j]);
                }
            }
        }
        #pragma unroll
        for (int r = 0; r < 8; ++r)
            ln_store(acc[r], gx, bx, o2 + (size_t)(m0 + r) * 256, lane);
    }
}

extern "C" void kernel_launch(void* const* d_in, const int* in_sizes, int n_in,
                              void* d_out, int out_size)
{
    // metadata order: h1_nodes, h2_nodes, batch1(int64, unused), batch2(int64, unused),
    //                 gamma, beta
    const float* h1  = (const float*)d_in[0];
    const float* h2  = (const float*)d_in[1];
    const float* gam = (const float*)d_in[4];
    const float* bet = (const float*)d_in[5];
    float* out = (float*)d_out;

    cudaFuncSetAttribute(interaction_kernel,
                         cudaFuncAttributeMaxDynamicSharedMemorySize, SMEM_BYTES);
    interaction_kernel<<<NB, NT, SMEM_BYTES>>>(h1, h2, gam, bet, out);
}

// round 9
// speedup vs baseline: 1.1929x; 1.1929x over previous
#include <cuda_runtime.h>
#include <cstdint>

typedef unsigned int u32;

#define NB 1024
#define N1 64
#define N2 128
#define DD 256
#define LN_EPS 1e-5f
#define ISCALE 0.0625f
#define NT 512
#define S_H 258
#define S_I 132

static constexpr int SH2_OFF     = N1 * S_H;
static constexpr int SI_OFF      = SH2_OFF + N2 * S_H;
static constexpr int SMEM_FLOATS = SI_OFF + N1 * S_I;
static constexpr int SMEM_BYTES  = SMEM_FLOATS * 4;      // 231936 B

// split a float pair into packed-bf16 hi and lo (lo = x - bf16(x)); x -> low 16 bits
__device__ __forceinline__ void split2(float x, float y, u32& hp, u32& lp) {
    asm("cvt.rn.bf16x2.f32 %0, %1, %2;" : "=r"(hp) : "f"(y), "f"(x));
    float hx = __uint_as_float(hp << 16);
    float hy = __uint_as_float(hp & 0xFFFF0000u);
    float lx = x - hx, ly = y - hy;
    asm("cvt.rn.bf16x2.f32 %0, %1, %2;" : "=r"(lp) : "f"(ly), "f"(lx));
}

__device__ __forceinline__ void mma16816(float* c, const u32* a, const u32* b) {
    asm volatile(
        "mma.sync.aligned.m16n8k16.row.col.f32.bf16.bf16.f32 "
        "{%0,%1,%2,%3}, {%4,%5,%6,%7}, {%8,%9}, {%0,%1,%2,%3};"
        : "+f"(c[0]), "+f"(c[1]), "+f"(c[2]), "+f"(c[3])
        : "r"(a[0]), "r"(a[1]), "r"(a[2]), "r"(a[3]), "r"(b[0]), "r"(b[1]));
}
// 3-term bf16 split product: AhiBhi + AloBhi + AhiBlo
__device__ __forceinline__ void mma3(float* c, const u32* aH, const u32* aL,
                                     const u32* bH, const u32* bL) {
    mma16816(c, aH, bH);
    mma16816(c, aL, bH);
    mma16816(c, aH, bL);
}

__global__ void __launch_bounds__(NT, 1)
interaction_mma_kernel(const float* __restrict__ h1g, const float* __restrict__ h2g,
                       const float* __restrict__ gam, const float* __restrict__ bet,
                       float* __restrict__ out)
{
    extern __shared__ float sm[];
    float* sh1 = sm;              // [64][S_H] fp32
    float* sh2 = sm + SH2_OFF;    // [128][S_H]
    float* sI  = sm + SI_OFF;     // [64][S_I]
    float2* scr = reinterpret_cast<float2*>(sm);   // LN scratch overlays sh1 (dead then)

    const int tid  = threadIdx.x;
    const int lane = tid & 31;
    const int wid  = tid >> 5;        // 0..15
    const int lq   = lane >> 2;       // 0..7  (row-within-fragment)
    const int lr   = lane & 3;        // 0..3  (k/col group)
    const int g    = blockIdx.x;

    const float4* h1v = reinterpret_cast<const float4*>(h1g) + (size_t)g * (N1 * DD / 4);
    const float4* h2v = reinterpret_cast<const float4*>(h2g) + (size_t)g * (N2 * DD / 4);
    float4* o1x = reinterpret_cast<float4*>(out) + (size_t)g * (N1 * DD / 2);
    float4* o2x = reinterpret_cast<float4*>(out) + (size_t)NB * (N1 * DD / 2)
                                                 + (size_t)g * (N2 * DD / 2);
    float* o1 = out + (size_t)g * (N1 * 2 * DD);                       // rows of 512
    float* o2 = out + (size_t)NB * (N1 * 2 * DD) + (size_t)g * (N2 * 2 * DD);

    // ---------------- Phase 1: global -> SMEM fp32, fused concat first-half copy ----------
    #pragma unroll 4
    for (int it = 0; it < (N1 * DD / 4) / NT; ++it) {    // 8 iters
        int idx = it * NT + tid;
        int row = idx >> 6, c4 = idx & 63;
        float4 v = h1v[idx];
        float* d = &sh1[row * S_H + 4 * c4];
        *reinterpret_cast<float2*>(d)     = make_float2(v.x, v.y);
        *reinterpret_cast<float2*>(d + 2) = make_float2(v.z, v.w);
        o1x[(size_t)row * 128 + c4] = v;
    }
    #pragma unroll 4
    for (int it = 0; it < (N2 * DD / 4) / NT; ++it) {    // 16 iters
        int idx = it * NT + tid;
        int row = idx >> 6, c4 = idx & 63;
        float4 v = h2v[idx];
        float* d = &sh2[row * S_H + 4 * c4];
        *reinterpret_cast<float2*>(d)     = make_float2(v.x, v.y);
        *reinterpret_cast<float2*>(d + 2) = make_float2(v.z, v.w);
        o2x[(size_t)row * 128 + c4] = v;
    }
    __syncthreads();

    // ================ GEMM1: I[64,128] = clip(scale * h1 @ h2^T), K=256 ===================
    // warp: m_tile = wid&3 (M=64/16), n-quarter = wid>>2 (4 n-tiles of 8 each)
    {
        const int m0 = (wid & 3) * 16;
        const int nq = wid >> 2;
        const int r  = m0 + lq;
        float c[4][4];
        #pragma unroll
        for (int j = 0; j < 4; ++j)
            #pragma unroll
            for (int i = 0; i < 4; ++i) c[j][i] = 0.f;

        #pragma unroll 1
        for (int k = 0; k < 16; ++k) {
            const int k0 = k * 16 + lr * 2;
            u32 aH[4], aL[4];
            float2 p;
            p = *reinterpret_cast<const float2*>(&sh1[r * S_H + k0]);           split2(p.x, p.y, aH[0], aL[0]);
            p = *reinterpret_cast<const float2*>(&sh1[(r + 8) * S_H + k0]);     split2(p.x, p.y, aH[1], aL[1]);
            p = *reinterpret_cast<const float2*>(&sh1[r * S_H + k0 + 8]);       split2(p.x, p.y, aH[2], aL[2]);
            p = *reinterpret_cast<const float2*>(&sh1[(r + 8) * S_H + k0 + 8]); split2(p.x, p.y, aH[3], aL[3]);
            #pragma unroll
            for (int j = 0; j < 4; ++j) {
                const int n = (nq * 4 + j) * 8 + lq;
                u32 bH[2], bL[2];
                p = *reinterpret_cast<const float2*>(&sh2[n * S_H + k0]);       split2(p.x, p.y, bH[0], bL[0]);
                p = *reinterpret_cast<const float2*>(&sh2[n * S_H + k0 + 8]);   split2(p.x, p.y, bH[1], bL[1]);
                mma3(c[j], aH, aL, bH, bL);
            }
        }
        #pragma unroll
        for (int j = 0; j < 4; ++j) {
            const int nc = (nq * 4 + j) * 8 + lr * 2;
            float v0 = fminf(fmaxf(c[j][0] * ISCALE, -10.f), 10.f);
            float v1 = fminf(fmaxf(c[j][1] * ISCALE, -10.f), 10.f);
            float v2 = fminf(fmaxf(c[j][2] * ISCALE, -10.f), 10.f);
            float v3 = fminf(fmaxf(c[j][3] * ISCALE, -10.f), 10.f);
            *reinterpret_cast<float2*>(&sI[r * S_I + nc])       = make_float2(v0, v1);
            *reinterpret_cast<float2*>(&sI[(r + 8) * S_I + nc]) = make_float2(v2, v3);
        }
    }
    __syncthreads();

    // ================ GEMM3: C3[128,256] = I^T @ h1, K=64 =================================
    // warp: m_tile = wid&7 (M=128/16), n-half = wid>>3 (16 n-tiles of 8)
    {
        const int m0 = (wid & 7) * 16;
        const int nh = wid >> 3;
        const int r  = m0 + lq;
        float c[16][4];
        #pragma unroll
        for (int j = 0; j < 16; ++j)
            #pragma unroll
            for (int i = 0; i < 4; ++i) c[j][i] = 0.f;

        #pragma unroll 1
        for (int k = 0; k < 4; ++k) {
            const int k0 = k * 16 + lr * 2;
            u32 aH[4], aL[4];
            // A = I^T: A[m][k] = I[k][m] (scalar column loads from sI)
            split2(sI[k0 * S_I + r],           sI[(k0 + 1) * S_I + r],       aH[0], aL[0]);
            split2(sI[k0 * S_I + r + 8],       sI[(k0 + 1) * S_I + r + 8],   aH[1], aL[1]);
            split2(sI[(k0 + 8) * S_I + r],     sI[(k0 + 9) * S_I + r],       aH[2], aL[2]);
            split2(sI[(k0 + 8) * S_I + r + 8], sI[(k0 + 9) * S_I + r + 8],   aH[3], aL[3]);
            #pragma unroll
            for (int j = 0; j < 16; ++j) {
                const int n = nh * 128 + j * 8 + lq;     // d column
                u32 bH[2], bL[2];
                // B[k][n] = h1[k][n] (column loads, stride S_H)
                split2(sh1[k0 * S_H + n],       sh1[(k0 + 1) * S_H + n], bH[0], bL[0]);
                split2(sh1[(k0 + 8) * S_H + n], sh1[(k0 + 9) * S_H + n], bH[1], bL[1]);
                mma3(c[j], aH, aL, bH, bL);
            }
        }
        __syncthreads();                         // sh1 dead -> scratch reuse OK
        // LN partials: rows r (c[.][0,1]) and r+8 (c[.][2,3]) over this warp's 128 cols
        float s0 = 0.f, q0 = 0.f, s1 = 0.f, q1 = 0.f;
        #pragma unroll
        for (int j = 0; j < 16; ++j) {
            s0 += c[j][0] + c[j][1];  q0 += c[j][0] * c[j][0] + c[j][1] * c[j][1];
            s1 += c[j][2] + c[j][3];  q1 += c[j][2] * c[j][2] + c[j][3] * c[j][3];
        }
        #pragma unroll
        for (int o = 1; o <= 2; o <<= 1) {
            s0 += __shfl_xor_sync(0xffffffffu, s0, o);
            q0 += __shfl_xor_sync(0xffffffffu, q0, o);
            s1 += __shfl_xor_sync(0xffffffffu, s1, o);
            q1 += __shfl_xor_sync(0xffffffffu, q1, o);
        }
        if (lr == 0) {
            scr[r * 2 + nh]       = make_float2(s0, q0);
            scr[(r + 8) * 2 + nh] = make_float2(s1, q1);
        }
        __syncthreads();
        float2 pa = scr[r * 2], pb = scr[r * 2 + 1];
        float2 pc = scr[(r + 8) * 2], pd = scr[(r + 8) * 2 + 1];
        float mu0 = (pa.x + pb.x) * (1.f / 256.f);
        float iv0 = rsqrtf((pa.y + pb.y) * (1.f / 256.f) - mu0 * mu0 + LN_EPS);
        float mu1 = (pc.x + pd.x) * (1.f / 256.f);
        float iv1 = rsqrtf((pc.y + pd.y) * (1.f / 256.f) - mu1 * mu1 + LN_EPS);
        #pragma unroll
        for (int j = 0; j < 16; ++j) {
            const int nc = nh * 128 + j * 8 + lr * 2;
            float2 gm = *reinterpret_cast<const float2*>(gam + nc);
            float2 bt = *reinterpret_cast<const float2*>(bet + nc);
            float2 u0 = make_float2((c[j][0] - mu0) * iv0 * gm.x + bt.x,
                                    (c[j][1] - mu0) * iv0 * gm.y + bt.y);
            float2 u1 = make_float2((c[j][2] - mu1) * iv1 * gm.x + bt.x,
                                    (c[j][3] - mu1) * iv1 * gm.y + bt.y);
            *reinterpret_cast<float2*>(o2 + (size_t)r * 512 + 256 + nc)       = u0;
            *reinterpret_cast<float2*>(o2 + (size_t)(r + 8) * 512 + 256 + nc) = u1;
        }
    }

    // ================ GEMM2: C2[64,256] = I @ h2, K=128 ===================================
    // warp: m_tile = wid&3 (M=64/16), n-quarter = wid>>2 (8 n-tiles of 8)
    {
        const int m0 = (wid & 3) * 16;
        const int nq = wid >> 2;
        const int r  = m0 + lq;
        float c[8][4];
        #pragma unroll
        for (int j = 0; j < 8; ++j)
            #pragma unroll
            for (int i = 0; i < 4; ++i) c[j][i] = 0.f;

        #pragma unroll 1
        for (int k = 0; k < 8; ++k) {
            const int k0 = k * 16 + lr * 2;
            u32 aH[4], aL[4];
            float2 p;
            p = *reinterpret_cast<const float2*>(&sI[r * S_I + k0]);           split2(p.x, p.y, aH[0], aL[0]);
            p = *reinterpret_cast<const float2*>(&sI[(r + 8) * S_I + k0]);     split2(p.x, p.y, aH[1], aL[1]);
            p = *reinterpret_cast<const float2*>(&sI[r * S_I + k0 + 8]);       split2(p.x, p.y, aH[2], aL[2]);
            p = *reinterpret_cast<const float2*>(&sI[(r + 8) * S_I + k0 + 8]); split2(p.x, p.y, aH[3], aL[3]);
            #pragma unroll
            for (int j = 0; j < 8; ++j) {
                const int n = nq * 64 + j * 8 + lq;      // d column
                u32 bH[2], bL[2];
                split2(sh2[k0 * S_H + n],       sh2[(k0 + 1) * S_H + n], bH[0], bL[0]);
                split2(sh2[(k0 + 8) * S_H + n], sh2[(k0 + 9) * S_H + n], bH[1], bL[1]);
                mma3(c[j], aH, aL, bH, bL);
            }
        }
        __syncthreads();                         // orders prior scratch reads before reuse
        float s0 = 0.f, q0 = 0.f, s1 = 0.f, q1 = 0.f;
        #pragma unroll
        for (int j = 0; j < 8; ++j) {
            s0 += c[j][0] + c[j][1];  q0 += c[j][0] * c[j][0] + c[j][1] * c[j][1];
            s1 += c[j][2] + c[j][3];  q1 += c[j][2] * c[j][2] + c[j][3] * c[j][3];
        }
        #pragma unroll
        for (int o = 1; o <= 2; o <<= 1) {
            s0 += __shfl_xor_sync(0xffffffffu, s0, o);
            q0 += __shfl_xor_sync(0xffffffffu, q0, o);
            s1 += __shfl_xor_sync(0xffffffffu, s1, o);
            q1 += __shfl_xor_sync(0xffffffffu, q1, o);
        }
        if (lr == 0) {
            scr[r * 4 + nq]       = make_float2(s0, q0);
            scr[(r + 8) * 4 + nq] = make_float2(s1, q1);
        }
        __syncthreads();
        float S0 = 0.f, Q0 = 0.f, S1 = 0.f, Q1 = 0.f;
        #pragma unroll
        for (int q = 0; q < 4; ++q) {
            float2 p0 = scr[r * 4 + q];       S0 += p0.x; Q0 += p0.y;
            float2 p1 = scr[(r + 8) * 4 + q]; S1 += p1.x; Q1 += p1.y;
        }
        float mu0 = S0 * (1.f / 256.f);
        float iv0 = rsqrtf(Q0 * (1.f / 256.f) - mu0 * mu0 + LN_EPS);
        float mu1 = S1 * (1.f / 256.f);
        float iv1 = rsqrtf(Q1 * (1.f / 256.f) - mu1 * mu1 + LN_EPS);
        #pragma unroll
        for (int j = 0; j < 8; ++j) {
            const int nc = nq * 64 + j * 8 + lr * 2;
            float2 gm = *reinterpret_cast<const float2*>(gam + nc);
            float2 bt = *reinterpret_cast<const float2*>(bet + nc);
            float2 u0 = make_float2((c[j][0] - mu0) * iv0 * gm.x + bt.x,
                                    (c[j][1] - mu0) * iv0 * gm.y + bt.y);
            float2 u1 = make_float2((c[j][2] - mu1) * iv1 * gm.x + bt.x,
                                    (c[j][3] - mu1) * iv1 * gm.y + bt.y);
            *reinterpret_cast<float2*>(o1 + (size_t)r * 512 + 256 + nc)       = u0;
            *reinterpret_cast<float2*>(o1 + (size_t)(r + 8) * 512 + 256 + nc) = u1;
        }
    }
}

extern "C" void kernel_launch(void* const* d_in, const int* in_sizes, int n_in,
                              void* d_out, int out_size)
{
    const float* h1  = (const float*)d_in[0];
    const float* h2  = (const float*)d_in[1];
    const float* gam = (const float*)d_in[4];
    const float* bet = (const float*)d_in[5];
    float* out = (float*)d_out;

    cudaFuncSetAttribute(interaction_mma_kernel,
                         cudaFuncAttributeMaxDynamicSharedMemorySize, SMEM_BYTES);
    interaction_mma_kernel<<<NB, NT, SMEM_BYTES>>>(h1, h2, gam, bet, out);
}

// round 10
// speedup vs baseline: 1.8644x; 1.5630x over previous
#include <cuda_runtime.h>
#include <cstdint>

typedef unsigned int u32;

#define NB 1024
#define LN_EPS 1e-5f
#define ISCALE 0.0625f
#define NT 512

// SMEM byte offsets. Rows hold [hi-plane | lo-plane] packed bf16, 16B chunks
// swizzled by (chunk ^ (row & 7)) for conflict-free ldmatrix.
#define H1O 0          // h1: 64 rows x 1024B (hi 512 | lo 512)
#define H2O 65536      // h2: 128 rows x 1024B
#define IRO 196608     // I : 64 rows x 512B  (hi 256 | lo 256)
#define SMEM_BYTES 229376

__device__ __forceinline__ u32 smem_u32(const void* p) {
    u32 a;
    asm("{ .reg .u64 t; cvta.to.shared.u64 t, %1; cvt.u32.u64 %0, t; }" : "=r"(a) : "l"(p));
    return a;
}
// split float pair into packed-bf16 hi and lo (lo = x - bf16(x)); x -> low 16 bits
__device__ __forceinline__ void split2(float x, float y, u32& hp, u32& lp) {
    asm("cvt.rn.bf16x2.f32 %0, %1, %2;" : "=r"(hp) : "f"(y), "f"(x));
    float hx = __uint_as_float(hp << 16);
    float hy = __uint_as_float(hp & 0xFFFF0000u);
    asm("cvt.rn.bf16x2.f32 %0, %1, %2;" : "=r"(lp) : "f"(y - hy), "f"(x - hx));
}
__device__ __forceinline__ void mma16816(float* c, const u32* a, const u32* b) {
    asm volatile(
        "mma.sync.aligned.m16n8k16.row.col.f32.bf16.bf16.f32 "
        "{%0,%1,%2,%3}, {%4,%5,%6,%7}, {%8,%9}, {%0,%1,%2,%3};"
        : "+f"(c[0]), "+f"(c[1]), "+f"(c[2]), "+f"(c[3])
        : "r"(a[0]), "r"(a[1]), "r"(a[2]), "r"(a[3]), "r"(b[0]), "r"(b[1]));
}
__device__ __forceinline__ void mma3(float* c, const u32* aH, const u32* aL,
                                     const u32* bH, const u32* bL) {
    mma16816(c, aH, bH);
    mma16816(c, aL, bH);
    mma16816(c, aH, bL);
}
__device__ __forceinline__ void ldm4(u32* r, u32 a) {
    asm volatile("ldmatrix.sync.aligned.m8n8.x4.shared.b16 {%0,%1,%2,%3}, [%4];"
        : "=r"(r[0]), "=r"(r[1]), "=r"(r[2]), "=r"(r[3]) : "r"(a));
}
__device__ __forceinline__ void ldm4t(u32* r, u32 a) {
    asm volatile("ldmatrix.sync.aligned.m8n8.x4.trans.shared.b16 {%0,%1,%2,%3}, [%4];"
        : "=r"(r[0]), "=r"(r[1]), "=r"(r[2]), "=r"(r[3]) : "r"(a));
}
__device__ __forceinline__ void ldm2(u32* r, u32 a) {
    asm volatile("ldmatrix.sync.aligned.m8n8.x2.shared.b16 {%0,%1}, [%2];"
        : "=r"(r[0]), "=r"(r[1]) : "r"(a));
}
__device__ __forceinline__ void ldm2t(u32* r, u32 a) {
    asm volatile("ldmatrix.sync.aligned.m8n8.x2.trans.shared.b16 {%0,%1}, [%2];"
        : "=r"(r[0]), "=r"(r[1]) : "r"(a));
}

__global__ void __launch_bounds__(NT, 1)
interaction_ldm_kernel(const float* __restrict__ h1g, const float* __restrict__ h2g,
                       const float* __restrict__ gam, const float* __restrict__ bet,
                       float* __restrict__ out)
{
    extern __shared__ char smc[];
    const u32 ub = smem_u32(smc);
    float2* scr = reinterpret_cast<float2*>(smc);    // LN scratch overlays h1 (dead then)

    const int tid  = threadIdx.x;
    const int lane = tid & 31;
    const int wid  = tid >> 5;
    const int lq   = lane >> 2;
    const int lr   = lane & 3;
    const int g    = blockIdx.x;

    const float4* h1v = reinterpret_cast<const float4*>(h1g) + (size_t)g * 4096;
    const float4* h2v = reinterpret_cast<const float4*>(h2g) + (size_t)g * 8192;
    float4* o1x = reinterpret_cast<float4*>(out) + (size_t)g * 8192;
    float4* o2x = reinterpret_cast<float4*>(out) + (size_t)NB * 8192 + (size_t)g * 16384;
    float* o1 = out + (size_t)g * 32768;
    float* o2 = out + (size_t)NB * 32768 + (size_t)g * 65536;

    // ---------------- Phase 1: load, copy-out, split to bf16 hi/lo planes ----------------
    #pragma unroll
    for (int it = 0; it < 8; ++it) {                  // h1: 64x256
        int idx = it * NT + tid, row = idx >> 6, c4 = idx & 63, d0 = c4 << 2;
        float4 v = h1v[idx];
        o1x[(size_t)row * 128 + c4] = v;
        u32 h01, l01, h23, l23;
        split2(v.x, v.y, h01, l01);
        split2(v.z, v.w, h23, l23);
        char* p = smc + H1O + (row << 10) + ((((d0 >> 3)) ^ (row & 7)) << 4) + ((d0 & 4) << 1);
        *reinterpret_cast<uint2*>(p)       = make_uint2(h01, h23);
        *reinterpret_cast<uint2*>(p + 512) = make_uint2(l01, l23);
    }
    #pragma unroll
    for (int it = 0; it < 16; ++it) {                 // h2: 128x256
        int idx = it * NT + tid, row = idx >> 6, c4 = idx & 63, d0 = c4 << 2;
        float4 v = h2v[idx];
        o2x[(size_t)row * 128 + c4] = v;
        u32 h01, l01, h23, l23;
        split2(v.x, v.y, h01, l01);
        split2(v.z, v.w, h23, l23);
        char* p = smc + H2O + (row << 10) + ((((d0 >> 3)) ^ (row & 7)) << 4) + ((d0 & 4) << 1);
        *reinterpret_cast<uint2*>(p)       = make_uint2(h01, h23);
        *reinterpret_cast<uint2*>(p + 512) = make_uint2(l01, l23);
    }
    __syncthreads();

    // ================ GEMM1: I[64,128] = clip(scale * h1 @ h2^T), K=256 ===================
    {
        const int m0 = (wid & 3) * 16;
        const int nq = wid >> 2;
        float c[4][4];
        #pragma unroll
        for (int j = 0; j < 4; ++j)
            #pragma unroll
            for (int i = 0; i < 4; ++i) c[j][i] = 0.f;

        const u32 arowb = ub + H1O + (u32)(m0 + (lane & 15)) * 1024u;
        const u32 lxor  = (u32)(lane & 7);
        u32 browb[4];
        #pragma unroll
        for (int j = 0; j < 4; ++j)
            browb[j] = ub + H2O + (u32)(((nq * 4 + j) * 8) + (lane & 7)) * 1024u;

        #pragma unroll 1
        for (int k = 0; k < 16; ++k) {
            u32 aaddr = arowb + (((2u * k + (lane >> 4)) ^ lxor) << 4);
            u32 aH[4], aL[4];
            ldm4(aH, aaddr);
            ldm4(aL, aaddr + 512);
            u32 cb = 2u * k + ((lane >> 3) & 1);
            #pragma unroll
            for (int j = 0; j < 4; ++j) {
                u32 baddr = browb[j] + ((cb ^ lxor) << 4);
                u32 bH[2], bL[2];
                ldm2(bH, baddr);
                ldm2(bL, baddr + 512);
                mma3(c[j], aH, aL, bH, bL);
            }
        }
        // epilogue: scale+clip, split, store to I planes (rows r and r+8)
        const int r = m0 + lq;
        #pragma unroll
        for (int j = 0; j < 4; ++j) {
            const int nc = (nq * 4 + j) * 8 + lr * 2;
            float v0 = fminf(fmaxf(c[j][0] * ISCALE, -10.f), 10.f);
            float v1 = fminf(fmaxf(c[j][1] * ISCALE, -10.f), 10.f);
            float v2 = fminf(fmaxf(c[j][2] * ISCALE, -10.f), 10.f);
            float v3 = fminf(fmaxf(c[j][3] * ISCALE, -10.f), 10.f);
            u32 h01, l01, h23, l23;
            split2(v0, v1, h01, l01);
            split2(v2, v3, h23, l23);
            char* p0 = smc + IRO + (r << 9) + (((nc >> 3) ^ (r & 7)) << 4) + ((nc & 7) << 1);
            *reinterpret_cast<u32*>(p0)              = h01;
            *reinterpret_cast<u32*>(p0 + 256)        = l01;
            *reinterpret_cast<u32*>(p0 + 4096)       = h23;   // row r+8: same swizzle (r&7 unchanged)
            *reinterpret_cast<u32*>(p0 + 4096 + 256) = l23;
        }
    }
    __syncthreads();

    // ================ GEMM3: C3[128,256] = I^T @ h1, K=64 =================================
    {
        const int mp0 = (wid & 7) * 16;
        const int nh  = wid >> 3;
        float c[16][4];
        #pragma unroll
        for (int j = 0; j < 16; ++j)
            #pragma unroll
            for (int i = 0; i < 4; ++i) c[j][i] = 0.f;

        const u32 lxor = (u32)(lane & 7);
        const u32 abase = ub + IRO + ((((u32)(mp0 >> 3) + ((lane >> 3) & 1)) ^ lxor) << 4);
        const int arofs = (lane & 7) + ((lane & 16) >> 1);
        const int brofs = (lane & 7) + (lane & 8);

        #pragma unroll 1
        for (int k = 0; k < 4; ++k) {
            const int k0 = 16 * k;
            u32 aaddr = abase + (u32)(k0 + arofs) * 512u;
            u32 aH[4], aL[4];
            ldm4t(aH, aaddr);
            ldm4t(aL, aaddr + 256);
            u32 bro = ub + H1O + (u32)(k0 + brofs) * 1024u;
            #pragma unroll
            for (int j = 0; j < 16; ++j) {
                u32 baddr = bro + (((u32)(nh * 16 + j) ^ lxor) << 4);
                u32 bH[2], bL[2];
                ldm2t(bH, baddr);
                ldm2t(bL, baddr + 512);
                mma3(c[j], aH, aL, bH, bL);
            }
        }
        __syncthreads();                      // h1 planes dead -> scratch reuse OK
        const int r = mp0 + lq;
        float s0 = 0.f, q0 = 0.f, s1 = 0.f, q1 = 0.f;
        #pragma unroll
        for (int j = 0; j < 16; ++j) {
            s0 += c[j][0] + c[j][1];  q0 += c[j][0] * c[j][0] + c[j][1] * c[j][1];
            s1 += c[j][2] + c[j][3];  q1 += c[j][2] * c[j][2] + c[j][3] * c[j][3];
        }
        #pragma unroll
        for (int o = 1; o <= 2; o <<= 1) {
            s0 += __shfl_xor_sync(0xffffffffu, s0, o);
            q0 += __shfl_xor_sync(0xffffffffu, q0, o);
            s1 += __shfl_xor_sync(0xffffffffu, s1, o);
            q1 += __shfl_xor_sync(0xffffffffu, q1, o);
        }
        if (lr == 0) {
            scr[r * 2 + nh]       = make_float2(s0, q0);
            scr[(r + 8) * 2 + nh] = make_float2(s1, q1);
        }
        __syncthreads();
        float2 pa = scr[r * 2], pb = scr[r * 2 + 1];
        float2 pc = scr[(r + 8) * 2], pd = scr[(r + 8) * 2 + 1];
        float mu0 = (pa.x + pb.x) * (1.f / 256.f);
        float iv0 = rsqrtf((pa.y + pb.y) * (1.f / 256.f) - mu0 * mu0 + LN_EPS);
        float mu1 = (pc.x + pd.x) * (1.f / 256.f);
        float iv1 = rsqrtf((pc.y + pd.y) * (1.f / 256.f) - mu1 * mu1 + LN_EPS);
        #pragma unroll
        for (int j = 0; j < 16; ++j) {
            const int nc = nh * 128 + j * 8 + lr * 2;
            float2 gm = *reinterpret_cast<const float2*>(gam + nc);
            float2 bt = *reinterpret_cast<const float2*>(bet + nc);
            float2 u0 = make_float2((c[j][0] - mu0) * iv0 * gm.x + bt.x,
                                    (c[j][1] - mu0) * iv0 * gm.y + bt.y);
            float2 u1 = make_float2((c[j][2] - mu1) * iv1 * gm.x + bt.x,
                                    (c[j][3] - mu1) * iv1 * gm.y + bt.y);
            *reinterpret_cast<float2*>(o2 + (size_t)r * 512 + 256 + nc)       = u0;
            *reinterpret_cast<float2*>(o2 + (size_t)(r + 8) * 512 + 256 + nc) = u1;
        }
    }

    // ================ GEMM2: C2[64,256] = I @ h2, K=128 ===================================
    {
        const int m0 = (wid & 3) * 16;
        const int nq = wid >> 2;
        float c[8][4];
        #pragma unroll
        for (int j = 0; j < 8; ++j)
            #pragma unroll
            for (int i = 0; i < 4; ++i) c[j][i] = 0.f;

        const u32 lxor = (u32)(lane & 7);
        const u32 arowb = ub + IRO + (u32)(m0 + (lane & 15)) * 512u;
        const int brofs = (lane & 7) + (lane & 8);

        #pragma unroll 1
        for (int k = 0; k < 8; ++k) {
            u32 aaddr = arowb + (((2u * k + (lane >> 4)) ^ lxor) << 4);
            u32 aH[4], aL[4];
            ldm4(aH, aaddr);
            ldm4(aL, aaddr + 256);
            u32 bro = ub + H2O + (u32)(16 * k + brofs) * 1024u;
            #pragma unroll
            for (int j = 0; j < 8; ++j) {
                u32 baddr = bro + (((u32)(nq * 8 + j) ^ lxor) << 4);
                u32 bH[2], bL[2];
                ldm2t(bH, baddr);
                ldm2t(bL, baddr + 512);
                mma3(c[j], aH, aL, bH, bL);
            }
        }
        __syncthreads();                      // orders prior scratch reads before reuse
        const int r = m0 + lq;
        float s0 = 0.f, q0 = 0.f, s1 = 0.f, q1 = 0.f;
        #pragma unroll
        for (int j = 0; j < 8; ++j) {
            s0 += c[j][0] + c[j][1];  q0 += c[j][0] * c[j][0] + c[j][1] * c[j][1];
            s1 += c[j][2] + c[j][3];  q1 += c[j][2] * c[j][2] + c[j][3] * c[j][3];
        }
        #pragma unroll
        for (int o = 1; o <= 2; o <<= 1) {
            s0 += __shfl_xor_sync(0xffffffffu, s0, o);
            q0 += __shfl_xor_sync(0xffffffffu, q0, o);
            s1 += __shfl_xor_sync(0xffffffffu, s1, o);
            q1 += __shfl_xor_sync(0xffffffffu, q1, o);
        }
        if (lr == 0) {
            scr[r * 4 + nq]       = make_float2(s0, q0);
            scr[(r + 8) * 4 + nq] = make_float2(s1, q1);
        }
        __syncthreads();
        float S0 = 0.f, Q0 = 0.f, S1 = 0.f, Q1 = 0.f;
        #pragma unroll
        for (int q = 0; q < 4; ++q) {
            float2 p0 = scr[r * 4 + q];       S0 += p0.x; Q0 += p0.y;
            float2 p1 = scr[(r + 8) * 4 + q]; S1 += p1.x; Q1 += p1.y;
        }
        float mu0 = S0 * (1.f / 256.f);
        float iv0 = rsqrtf(Q0 * (1.f / 256.f) - mu0 * mu0 + LN_EPS);
        float mu1 = S1 * (1.f / 256.f);
        float iv1 = rsqrtf(Q1 * (1.f / 256.f) - mu1 * mu1 + LN_EPS);
        #pragma unroll
        for (int j = 0; j < 8; ++j) {
            const int nc = nq * 64 + j * 8 + lr * 2;
            float2 gm = *reinterpret_cast<const float2*>(gam + nc);
            float2 bt = *reinterpret_cast<const float2*>(bet + nc);
            float2 u0 = make_float2((c[j][0] - mu0) * iv0 * gm.x + bt.x,
                                    (c[j][1] - mu0) * iv0 * gm.y + bt.y);
            float2 u1 = make_float2((c[j][2] - mu1) * iv1 * gm.x + bt.x,
                                    (c[j][3] - mu1) * iv1 * gm.y + bt.y);
            *reinterpret_cast<float2*>(o1 + (size_t)r * 512 + 256 + nc)       = u0;
            *reinterpret_cast<float2*>(o1 + (size_t)(r + 8) * 512 + 256 + nc) = u1;
        }
    }
}

extern "C" void kernel_launch(void* const* d_in, const int* in_sizes, int n_in,
                              void* d_out, int out_size)
{
    const float* h1  = (const float*)d_in[0];
    const float* h2  = (const float*)d_in[1];
    const float* gam = (const float*)d_in[4];
    const float* bet = (const float*)d_in[5];
    float* out = (float*)d_out;

    cudaFuncSetAttribute(interaction_ldm_kernel,
                         cudaFuncAttributeMaxDynamicSharedMemorySize, SMEM_BYTES);
    interaction_ldm_kernel<<<NB, NT, SMEM_BYTES>>>(h1, h2, gam, bet, out);
}